// round 15
// baseline (speedup 1.0000x reference)
#include <cuda_runtime.h>
#include <cuda_fp16.h>

#define NN 100000
#define NE 1600000
#define IN_CH 128
#define HID 64
#define LAT 32

#define SCAN_BLK 512
#define SCAN_NB ((NN + SCAN_BLK - 1) / SCAN_BLK)   // 196
#define NEP (NE + 8 * NN)                          // padded edge capacity

// Scratch (static __device__ — no allocations allowed)
__device__ int     g_stride;              // 1 = edge_index int32, 2 = int64
__device__ int     g_deg[NN];
__device__ int     g_rowptr[NN + 1];      // padded CSR offsets (multiples of 8)
__device__ int     g_cursor[NN];
__device__ int     g_blocksums[SCAN_NB];
__device__ int     g_srcbuf[NEP];         // per-edge source index (pad = NN)
__device__ float   g_dis[NN];
__device__ __half2 g_ha[(NN + 1) * 32];   // dis*h1 fp16; ghost node NN stays 0
__device__ __half2 g_hb[(NN + 1) * 32];   // dis*relu(...) fp16; ghost stays 0

struct alignas(16) H8 { __half2 h[4]; };

// ---------------------------------------------------------------------------
__device__ __forceinline__ unsigned smem_u32(const void* p) {
    return (unsigned)__cvta_generic_to_shared(p);
}
__device__ __forceinline__ H8 cvt8(float4 f0, float4 f1) {
    H8 h;
    h.h[0] = __floats2half2_rn(f0.x, f0.y);
    h.h[1] = __floats2half2_rn(f0.z, f0.w);
    h.h[2] = __floats2half2_rn(f1.x, f1.y);
    h.h[3] = __floats2half2_rn(f1.z, f1.w);
    return h;
}

// ---------------------------------------------------------------------------
// Zero degrees; block 0 warp 0 detects edge_index dtype (int64 → odd words 0).
__global__ void k_zero_detect(const int* __restrict__ ei) {
    int i = blockIdx.x * blockDim.x + threadIdx.x;
    if (i < NN) g_deg[i] = 0;
    if (blockIdx.x == 0 && threadIdx.x < 32) {
        int lane = threadIdx.x;
        int v = ei[2 * lane + 1];
        unsigned m = __ballot_sync(0xffffffffu, v != 0);
        if (lane == 0) g_stride = (m == 0u) ? 2 : 1;
    }
}

__global__ void k_count_deg(const int* __restrict__ ei) {
    int e = blockIdx.x * blockDim.x + threadIdx.x;
    if (e >= NE) return;
    int st = g_stride;
    int c = ei[(size_t)st * NE + (size_t)e * st];   // target node
    atomicAdd(&g_deg[c], 1);
}

// Per-block exclusive scan of PADDED degrees -> g_rowptr (local part).
// Also computes dis = rsqrt(deg+1) so gemm1 can run right after this.
__global__ void k_scan_local() {
    __shared__ int s[SCAN_BLK];
    int t = threadIdx.x;
    int i = blockIdx.x * SCAN_BLK + t;
    int deg = (i < NN) ? g_deg[i] : 0;
    if (i < NN) g_dis[i] = rsqrtf((float)deg + 1.0f);
    int v = (deg + 7) & ~7;                          // pad to multiple of 8
    s[t] = v;
    __syncthreads();
#pragma unroll
    for (int off = 1; off < SCAN_BLK; off <<= 1) {
        int add = (t >= off) ? s[t - off] : 0;
        __syncthreads();
        s[t] += add;
        __syncthreads();
    }
    if (i < NN) g_rowptr[i] = s[t] - v;   // exclusive (local)
    if (t == SCAN_BLK - 1) g_blocksums[blockIdx.x] = s[t];
}

// ---------------------------------------------------------------------------
// h1 = x @ W1 via HMMA (mma.sync m16n8k16, fp16 in, fp32 acc).
// 256 threads, 128 rows/block. Staging uses 8-deep batched LDG.128 for MLP.
// Epilogue: ĥ = fp16(dis * h1) → g_ha.
__global__ void k_gemm1(const float* __restrict__ x, const float* __restrict__ W) {
    __shared__ alignas(16) __half sA[128 * 128];   // 32 KB: [row][k] swizzled
    __shared__ alignas(16) __half sW[128 * 64];    // 16 KB: [k][n]  swizzled
    int tid = threadIdx.x;
    int base0 = blockIdx.x * 128;

    // Stage x tile with deep MLP: 2048 chunks, 2 batches × (8 LDG.128 → cvt/STS).
#pragma unroll
    for (int b = 0; b < 2; b++) {
        float4 f[8];
#pragma unroll
        for (int q = 0; q < 4; q++) {
            int idx = tid + (b * 4 + q) * 256;
            int row = idx >> 4, c = idx & 15;
            int grow = base0 + row;
            if (grow >= NN) grow = NN - 1;         // junk ok, stores guarded
            const float4* src = reinterpret_cast<const float4*>(
                x + (size_t)grow * IN_CH + c * 8);
            f[2 * q] = src[0];
            f[2 * q + 1] = src[1];
        }
#pragma unroll
        for (int q = 0; q < 4; q++) {
            int idx = tid + (b * 4 + q) * 256;
            int row = idx >> 4, c = idx & 15;
            H8 h = cvt8(f[2 * q], f[2 * q + 1]);
            *reinterpret_cast<H8*>(&sA[row * 128 + ((c ^ (row & 7)) * 8)]) = h;
        }
    }
    // Stage W tile: 1024 chunks; chunk (k, c) at k*128B + (c^(k&7))*16B.
    for (int idx = tid; idx < 128 * 8; idx += 256) {
        int k = idx >> 3, c = idx & 7;
        const float4* src = reinterpret_cast<const float4*>(W + k * HID + c * 8);
        H8 h = cvt8(src[0], src[1]);
        *reinterpret_cast<H8*>(&sW[k * 64 + ((c ^ (k & 7)) * 8)]) = h;
    }
    __syncthreads();

    int warp = tid >> 5;
    int lane = tid & 31;
    int wrow = warp * 16;

    float acc[8][4];
#pragma unroll
    for (int n = 0; n < 8; n++)
#pragma unroll
        for (int j = 0; j < 4; j++) acc[n][j] = 0.0f;

    int a_t = lane >> 3, a_r = lane & 7;
    int a_row = wrow + (a_t & 1) * 8 + a_r;
    int a_chsel = a_t >> 1;
    int b_kr = (a_t & 1) * 8 + a_r;
    int b_csel = a_t >> 1;

#pragma unroll
    for (int kc = 0; kc < 8; kc++) {
        unsigned a0, a1, a2, a3;
        {
            int chunk = 2 * kc + a_chsel;
            unsigned addr = smem_u32(&sA[a_row * 128 + ((chunk ^ (a_row & 7)) * 8)]);
            asm volatile("ldmatrix.sync.aligned.m8n8.x4.shared.b16 {%0,%1,%2,%3}, [%4];"
                         : "=r"(a0), "=r"(a1), "=r"(a2), "=r"(a3) : "r"(addr));
        }
        int krow = 16 * kc + b_kr;
#pragma unroll
        for (int np = 0; np < 4; np++) {
            unsigned b0, b1, b2, b3;
            int chunk = 2 * np + b_csel;
            unsigned addr = smem_u32(&sW[krow * 64 + ((chunk ^ (krow & 7)) * 8)]);
            asm volatile("ldmatrix.sync.aligned.m8n8.x4.trans.shared.b16 {%0,%1,%2,%3}, [%4];"
                         : "=r"(b0), "=r"(b1), "=r"(b2), "=r"(b3) : "r"(addr));
            asm volatile("mma.sync.aligned.m16n8k16.row.col.f32.f16.f16.f32 "
                         "{%0,%1,%2,%3}, {%4,%5,%6,%7}, {%8,%9}, {%0,%1,%2,%3};"
                         : "+f"(acc[2 * np][0]), "+f"(acc[2 * np][1]),
                           "+f"(acc[2 * np][2]), "+f"(acc[2 * np][3])
                         : "r"(a0), "r"(a1), "r"(a2), "r"(a3), "r"(b0), "r"(b1));
            asm volatile("mma.sync.aligned.m16n8k16.row.col.f32.f16.f16.f32 "
                         "{%0,%1,%2,%3}, {%4,%5,%6,%7}, {%8,%9}, {%0,%1,%2,%3};"
                         : "+f"(acc[2 * np + 1][0]), "+f"(acc[2 * np + 1][1]),
                           "+f"(acc[2 * np + 1][2]), "+f"(acc[2 * np + 1][3])
                         : "r"(a0), "r"(a1), "r"(a2), "r"(a3), "r"(b2), "r"(b3));
        }
    }

    int r0 = wrow + (lane >> 2);
    int cq = lane & 3;
#pragma unroll
    for (int half = 0; half < 2; half++) {
        int node = base0 + r0 + half * 8;
        if (node < NN) {
            float d = g_dis[node];
#pragma unroll
            for (int nt = 0; nt < 8; nt++) {
                float v0 = acc[nt][2 * half + 0] * d;
                float v1 = acc[nt][2 * half + 1] * d;
                g_ha[(size_t)node * 32 + nt * 4 + cq] = __floats2half2_rn(v0, v1);
            }
        }
    }
}

// Finalize: every block redundantly scans the 196 block sums in smem, then
// rowptr += prefix; cursor = rowptr; pad slots get ghost source NN.
__global__ void k_finalize_csr() {
    __shared__ int s[256];
    int t = threadIdx.x;
    int bv = (t < SCAN_NB) ? g_blocksums[t] : 0;
    s[t] = bv;
    __syncthreads();
#pragma unroll
    for (int off = 1; off < 256; off <<= 1) {
        int add = (t >= off) ? s[t - off] : 0;
        __syncthreads();
        s[t] += add;
        __syncthreads();
    }
    int i = blockIdx.x * blockDim.x + t;
    if (i < NN) {
        int sb = i >> 9;
        int prefix = (sb > 0) ? s[sb - 1] : 0;
        int rp = g_rowptr[i] + prefix;
        g_rowptr[i] = rp;
        g_cursor[i] = rp;
        int deg = g_deg[i];
        int pdeg = (deg + 7) & ~7;
        for (int j = rp + deg; j < rp + pdeg; j++)
            g_srcbuf[j] = NN;                        // ghost node: features 0
    }
    if (i == 0) g_rowptr[NN] = s[SCAN_NB - 1];
}

// Scatter edge sources into destination-sorted padded order (4B records).
__global__ void k_scatter(const int* __restrict__ ei) {
    int e = blockIdx.x * blockDim.x + threadIdx.x;
    if (e >= NE) return;
    int st = g_stride;
    int r = ei[(size_t)e * st];                     // source
    int c = ei[(size_t)st * NE + (size_t)e * st];   // target
    int pos = atomicAdd(&g_cursor[c], 1);
    g_srcbuf[pos] = r;
}

// ---------------------------------------------------------------------------
// Warp-level CSR aggregation core over PADDED segments (multiples of 8).
// Returns fp32 pair (2 channels per lane) for `node`.
__device__ __forceinline__ float2 agg_node(const __half2* __restrict__ hin,
                                           int node, int lane) {
    int e = g_rowptr[node];
    int end = g_rowptr[node + 1];

    float2 self = __half22float2(hin[(size_t)node * 32 + lane]);
    float acx = self.x, acy = self.y;
    float bcx = 0.0f, bcy = 0.0f;

    const int* __restrict__ sp = g_srcbuf;
    for (; e < end; e += 8) {
        int4 a = *reinterpret_cast<const int4*>(sp + e);
        int4 b = *reinterpret_cast<const int4*>(sp + e + 4);
        float2 v0 = __half22float2(hin[(size_t)a.x * 32 + lane]);
        float2 v1 = __half22float2(hin[(size_t)a.y * 32 + lane]);
        float2 v2 = __half22float2(hin[(size_t)a.z * 32 + lane]);
        float2 v3 = __half22float2(hin[(size_t)a.w * 32 + lane]);
        float2 v4 = __half22float2(hin[(size_t)b.x * 32 + lane]);
        float2 v5 = __half22float2(hin[(size_t)b.y * 32 + lane]);
        float2 v6 = __half22float2(hin[(size_t)b.z * 32 + lane]);
        float2 v7 = __half22float2(hin[(size_t)b.w * 32 + lane]);
        acx += v0.x; acy += v0.y;
        bcx += v1.x; bcy += v1.y;
        acx += v2.x; acy += v2.y;
        bcx += v3.x; bcy += v3.y;
        acx += v4.x; acy += v4.y;
        bcx += v5.x; bcy += v5.y;
        acx += v6.x; acy += v6.y;
        bcx += v7.x; bcy += v7.y;
    }
    float d = g_dis[node];
    return make_float2(d * (acx + bcx), d * (acy + bcy));
}

// agg1: g_hb = fp16(dis * relu(P ĥa + b1))  (pre-scaled for next gather)
__global__ void k_agg1(const float* __restrict__ bias) {
    int node = blockIdx.x * 8 + (threadIdx.x >> 5);   // 12500*8 == NN exactly
    int lane = threadIdx.x & 31;
    float2 r = agg_node(g_ha, node, lane);
    float2 b = reinterpret_cast<const float2*>(bias)[lane];
    float d = g_dis[node];
    float hx = fmaxf(r.x + b.x, 0.0f);
    float hy = fmaxf(r.y + b.y, 0.0f);
    g_hb[(size_t)node * 32 + lane] = __floats2half2_rn(d * hx, d * hy);
}

// ---------------------------------------------------------------------------
// FUSED agg2 + gemm2: block owns 128 nodes. Each of 8 warps aggregates 16
// nodes (P ĥb, dis-scaled) writing fp16 results straight into the swizzled
// smem A-tile; then HMMA: [mu|lv] = A @ [Wmu|Wlv] + [bmu|blv].
__global__ void k_agg2gemm2(const float* __restrict__ Wmu, const float* __restrict__ bmu,
                            const float* __restrict__ Wlv, const float* __restrict__ blv,
                            float* __restrict__ out) {
    __shared__ alignas(16) __half sA[128 * 64];    // 16 KB: [row][k] swizzled
    __shared__ alignas(16) __half sW[64 * 64];     // 8 KB:  [k][n]  swizzled
    __shared__ alignas(16) float sB[64];
    int tid = threadIdx.x;
    int base0 = blockIdx.x * 128;
    int warp = tid >> 5;
    int lane = tid & 31;

    // Stage W (combined mu|lv) + bias.
    for (int idx = tid; idx < 64 * 8; idx += 256) {
        int k = idx >> 3, c = idx & 7;
        const float* src = (c < 4) ? (Wmu + k * LAT + c * 8)
                                   : (Wlv + k * LAT + (c - 4) * 8);
        const float4* s4 = reinterpret_cast<const float4*>(src);
        H8 h = cvt8(s4[0], s4[1]);
        *reinterpret_cast<H8*>(&sW[k * 64 + ((c ^ (k & 7)) * 8)]) = h;
    }
    if (tid < 64) sB[tid] = (tid < 32) ? bmu[tid] : blv[tid - 32];

    // Aggregate: warp w handles rows w*16 .. w*16+15 of the A tile.
    // Lane's half2 (channels 2*lane, 2*lane+1) lands in 16B chunk lane>>2 at
    // half-offset (lane&3)*2 — swizzled per row; warp spans 128B → no conflicts.
#pragma unroll 1
    for (int j = 0; j < 16; j++) {
        int row = warp * 16 + j;
        int node = base0 + row;
        if (node < NN) {
            float2 r = agg_node(g_hb, node, lane);
            int chunk = lane >> 2;
            sA[row * 64 + ((chunk ^ (row & 7)) * 8) + (lane & 3) * 2]     = __float2half_rn(r.x);
            sA[row * 64 + ((chunk ^ (row & 7)) * 8) + (lane & 3) * 2 + 1] = __float2half_rn(r.y);
        }
        // rows >= NN: junk smem only feeds guarded-out accumulator rows
    }
    __syncthreads();

    int wrow = warp * 16;
    float acc[8][4];
#pragma unroll
    for (int n = 0; n < 8; n++)
#pragma unroll
        for (int j = 0; j < 4; j++) acc[n][j] = 0.0f;

    int a_t = lane >> 3, a_r = lane & 7;
    int a_row = wrow + (a_t & 1) * 8 + a_r;
    int a_chsel = a_t >> 1;
    int b_kr = (a_t & 1) * 8 + a_r;
    int b_csel = a_t >> 1;

#pragma unroll
    for (int kc = 0; kc < 4; kc++) {
        unsigned a0, a1, a2, a3;
        {
            int chunk = 2 * kc + a_chsel;
            unsigned addr = smem_u32(&sA[a_row * 64 + ((chunk ^ (a_row & 7)) * 8)]);
            asm volatile("ldmatrix.sync.aligned.m8n8.x4.shared.b16 {%0,%1,%2,%3}, [%4];"
                         : "=r"(a0), "=r"(a1), "=r"(a2), "=r"(a3) : "r"(addr));
        }
        int krow = 16 * kc + b_kr;
#pragma unroll
        for (int np = 0; np < 4; np++) {
            unsigned b0, b1, b2, b3;
            int chunk = 2 * np + b_csel;
            unsigned addr = smem_u32(&sW[krow * 64 + ((chunk ^ (krow & 7)) * 8)]);
            asm volatile("ldmatrix.sync.aligned.m8n8.x4.trans.shared.b16 {%0,%1,%2,%3}, [%4];"
                         : "=r"(b0), "=r"(b1), "=r"(b2), "=r"(b3) : "r"(addr));
            asm volatile("mma.sync.aligned.m16n8k16.row.col.f32.f16.f16.f32 "
                         "{%0,%1,%2,%3}, {%4,%5,%6,%7}, {%8,%9}, {%0,%1,%2,%3};"
                         : "+f"(acc[2 * np][0]), "+f"(acc[2 * np][1]),
                           "+f"(acc[2 * np][2]), "+f"(acc[2 * np][3])
                         : "r"(a0), "r"(a1), "r"(a2), "r"(a3), "r"(b0), "r"(b1));
            asm volatile("mma.sync.aligned.m16n8k16.row.col.f32.f16.f16.f32 "
                         "{%0,%1,%2,%3}, {%4,%5,%6,%7}, {%8,%9}, {%0,%1,%2,%3};"
                         : "+f"(acc[2 * np + 1][0]), "+f"(acc[2 * np + 1][1]),
                           "+f"(acc[2 * np + 1][2]), "+f"(acc[2 * np + 1][3])
                         : "r"(a0), "r"(a1), "r"(a2), "r"(a3), "r"(b2), "r"(b3));
        }
    }

    // Epilogue: c = nt*8 + (lane&3)*2 (+1). nt<4 → mu, nt>=4 → lv.
    int r0 = wrow + (lane >> 2);
    int cq = lane & 3;
#pragma unroll
    for (int half = 0; half < 2; half++) {
        int node = base0 + r0 + half * 8;
        if (node < NN) {
#pragma unroll
            for (int nt = 0; nt < 8; nt++) {
                int c = nt * 8 + cq * 2;
                float2 v;
                v.x = acc[nt][2 * half + 0] + sB[c];
                v.y = acc[nt][2 * half + 1] + sB[c + 1];
                if (c < 32)
                    *reinterpret_cast<float2*>(&out[(size_t)node * LAT + c]) = v;
                else
                    *reinterpret_cast<float2*>(
                        &out[(size_t)NN * LAT + (size_t)node * LAT + (c - 32)]) = v;
            }
        }
    }
}

// ---------------------------------------------------------------------------
extern "C" void kernel_launch(void* const* d_in, const int* in_sizes, int n_in,
                              void* d_out, int out_size) {
    const float* x    = (const float*)d_in[0];
    const int*   ei   = (const int*)d_in[1];    // int32 or int64 (detected)
    const float* W1   = (const float*)d_in[2];
    const float* b1   = (const float*)d_in[3];
    const float* Wmu  = (const float*)d_in[4];
    const float* bmu  = (const float*)d_in[5];
    const float* Wlv  = (const float*)d_in[6];
    const float* blv  = (const float*)d_in[7];
    float*       out  = (float*)d_out;

    k_zero_detect<<<(NN + 255) / 256, 256>>>(ei);       // 1
    k_count_deg<<<(NE + 255) / 256, 256>>>(ei);         // 2
    k_scan_local<<<SCAN_NB, SCAN_BLK>>>();              // 3 (also dis)
    k_gemm1<<<(NN + 127) / 128, 256>>>(x, W1);          // 4 ← ncu profiles this
    k_finalize_csr<<<(NN + 255) / 256, 256>>>();        // 5
    k_scatter<<<(NE + 255) / 256, 256>>>(ei);           // 6
    k_agg1<<<NN / 8, 256>>>(b1);                        // 7
    k_agg2gemm2<<<(NN + 127) / 128, 256>>>(Wmu, bmu, Wlv, blv, out);  // 8
}

// round 16
// speedup vs baseline: 1.1206x; 1.1206x over previous
#include <cuda_runtime.h>
#include <cuda_fp16.h>

#define NN 100000
#define NE 1600000
#define IN_CH 128
#define HID 64
#define LAT 32

#define SCAN_BLK 512
#define SCAN_NB ((NN + SCAN_BLK - 1) / SCAN_BLK)   // 196
#define NEP (NE + 8 * NN)                          // padded edge capacity
#define GB1 ((NN + 127) / 128)                     // 782 gemm1 blocks
#define SCAT_BLKS ((NE + 1023) / 1024)             // 1563 scatter blocks

// Scratch (static __device__ — no allocations allowed)
__device__ int     g_stride;              // 1 = edge_index int32, 2 = int64
__device__ int     g_deg[NN];
__device__ int     g_rowptr[NN + 1];      // padded CSR offsets (multiples of 8)
__device__ int     g_cursor[NN];
__device__ int     g_blocksums[SCAN_NB];
__device__ int     g_srcbuf[NEP];         // per-edge source index (pad = NN)
__device__ float   g_dis[NN];
__device__ __half2 g_ha[(NN + 1) * 32];   // dis*h1 fp16; later agg2 out (fp16)
__device__ __half2 g_hb[(NN + 1) * 32];   // dis*relu(...) fp16; ghost stays 0

struct alignas(16) H8 { __half2 h[4]; };

// ---------------------------------------------------------------------------
__device__ __forceinline__ unsigned smem_u32(const void* p) {
    return (unsigned)__cvta_generic_to_shared(p);
}
__device__ __forceinline__ H8 cvt8(float4 f0, float4 f1) {
    H8 h;
    h.h[0] = __floats2half2_rn(f0.x, f0.y);
    h.h[1] = __floats2half2_rn(f0.z, f0.w);
    h.h[2] = __floats2half2_rn(f1.x, f1.y);
    h.h[3] = __floats2half2_rn(f1.z, f1.w);
    return h;
}

// ---------------------------------------------------------------------------
// Zero degrees; block 0 warp 0 detects edge_index dtype (int64 → odd words 0).
__global__ void k_zero_detect(const int* __restrict__ ei) {
    int i = blockIdx.x * blockDim.x + threadIdx.x;
    if (i < NN) g_deg[i] = 0;
    if (blockIdx.x == 0 && threadIdx.x < 32) {
        int lane = threadIdx.x;
        int v = ei[2 * lane + 1];
        unsigned m = __ballot_sync(0xffffffffu, v != 0);
        if (lane == 0) g_stride = (m == 0u) ? 2 : 1;
    }
}

__global__ void k_count_deg(const int* __restrict__ ei) {
    int e = blockIdx.x * blockDim.x + threadIdx.x;
    if (e >= NE) return;
    int st = g_stride;
    int c = ei[(size_t)st * NE + (size_t)e * st];   // target node
    atomicAdd(&g_deg[c], 1);
}

// Per-block exclusive scan of PADDED degrees -> g_rowptr (local part).
// Also computes dis = rsqrt(deg+1).
__global__ void k_scan_local() {
    __shared__ int s[SCAN_BLK];
    int t = threadIdx.x;
    int i = blockIdx.x * SCAN_BLK + t;
    int deg = (i < NN) ? g_deg[i] : 0;
    if (i < NN) g_dis[i] = rsqrtf((float)deg + 1.0f);
    int v = (deg + 7) & ~7;                          // pad to multiple of 8
    s[t] = v;
    __syncthreads();
#pragma unroll
    for (int off = 1; off < SCAN_BLK; off <<= 1) {
        int add = (t >= off) ? s[t - off] : 0;
        __syncthreads();
        s[t] += add;
        __syncthreads();
    }
    if (i < NN) g_rowptr[i] = s[t] - v;   // exclusive (local)
    if (t == SCAN_BLK - 1) g_blocksums[blockIdx.x] = s[t];
}

// Finalize: every block redundantly scans the 196 block sums in smem, then
// rowptr += prefix; cursor = rowptr; pad slots get ghost source NN.
__global__ void k_finalize_csr() {
    __shared__ int s[256];
    int t = threadIdx.x;
    int bv = (t < SCAN_NB) ? g_blocksums[t] : 0;
    s[t] = bv;
    __syncthreads();
#pragma unroll
    for (int off = 1; off < 256; off <<= 1) {
        int add = (t >= off) ? s[t - off] : 0;
        __syncthreads();
        s[t] += add;
        __syncthreads();
    }
    int i = blockIdx.x * blockDim.x + t;
    if (i < NN) {
        int sb = i >> 9;
        int prefix = (sb > 0) ? s[sb - 1] : 0;
        int rp = g_rowptr[i] + prefix;
        g_rowptr[i] = rp;
        g_cursor[i] = rp;
        int deg = g_deg[i];
        int pdeg = (deg + 7) & ~7;
        for (int j = rp + deg; j < rp + pdeg; j++)
            g_srcbuf[j] = NN;                        // ghost node: features 0
    }
    if (i == 0) g_rowptr[NN] = s[SCAN_NB - 1];
}

// ---------------------------------------------------------------------------
// FAT KERNEL: blocks [0, GB1) run gemm1 (h1 = x@W1 via HMMA, ĥ→g_ha);
// blocks [GB1, GB1+SCAT_BLKS) run edge scatter (4 edges/thread, batched).
// The two works are independent (gemm1 needs only dis; scatter needs cursor)
// and run concurrently on the SM pool — overlapping ~20µs of scatter with
// ~22µs of gemm1 without any barrier coupling.
__global__ void k_gemm1_scatter(const float* __restrict__ x,
                                const float* __restrict__ W,
                                const int* __restrict__ ei) {
    __shared__ alignas(16) __half sA[128 * 128];   // 32 KB: [row][k] swizzled
    __shared__ alignas(16) __half sW[128 * 64];    // 16 KB: [k][n]  swizzled
    int tid = threadIdx.x;

    if (blockIdx.x >= GB1) {
        // ---- scatter path ----
        int base = (blockIdx.x - GB1) * 1024 + tid;
        int st = g_stride;
        int rr[4], cc[4];
#pragma unroll
        for (int j = 0; j < 4; j++) {
            int e = base + j * 256;
            int es = (e < NE) ? e : NE - 1;
            rr[j] = ei[(size_t)es * st];
            cc[j] = ei[(size_t)st * NE + (size_t)es * st];
        }
#pragma unroll
        for (int j = 0; j < 4; j++) {
            int e = base + j * 256;
            if (e < NE) {
                int pos = atomicAdd(&g_cursor[cc[j]], 1);
                g_srcbuf[pos] = rr[j];
            }
        }
        return;
    }

    // ---- gemm1 path ----
    int base0 = blockIdx.x * 128;

    // Stage x tile with deep MLP: 2048 chunks, 2 batches × (8 LDG.128 → cvt/STS).
#pragma unroll
    for (int b = 0; b < 2; b++) {
        float4 f[8];
#pragma unroll
        for (int q = 0; q < 4; q++) {
            int idx = tid + (b * 4 + q) * 256;
            int row = idx >> 4, c = idx & 15;
            int grow = base0 + row;
            if (grow >= NN) grow = NN - 1;         // junk ok, stores guarded
            const float4* src = reinterpret_cast<const float4*>(
                x + (size_t)grow * IN_CH + c * 8);
            f[2 * q] = src[0];
            f[2 * q + 1] = src[1];
        }
#pragma unroll
        for (int q = 0; q < 4; q++) {
            int idx = tid + (b * 4 + q) * 256;
            int row = idx >> 4, c = idx & 15;
            H8 h = cvt8(f[2 * q], f[2 * q + 1]);
            *reinterpret_cast<H8*>(&sA[row * 128 + ((c ^ (row & 7)) * 8)]) = h;
        }
    }
    // Stage W tile: 1024 chunks; chunk (k, c) at k*128B + (c^(k&7))*16B.
    for (int idx = tid; idx < 128 * 8; idx += 256) {
        int k = idx >> 3, c = idx & 7;
        const float4* src = reinterpret_cast<const float4*>(W + k * HID + c * 8);
        H8 h = cvt8(src[0], src[1]);
        *reinterpret_cast<H8*>(&sW[k * 64 + ((c ^ (k & 7)) * 8)]) = h;
    }
    __syncthreads();

    int warp = tid >> 5;
    int lane = tid & 31;
    int wrow = warp * 16;

    float acc[8][4];
#pragma unroll
    for (int n = 0; n < 8; n++)
#pragma unroll
        for (int j = 0; j < 4; j++) acc[n][j] = 0.0f;

    int a_t = lane >> 3, a_r = lane & 7;
    int a_row = wrow + (a_t & 1) * 8 + a_r;
    int a_chsel = a_t >> 1;
    int b_kr = (a_t & 1) * 8 + a_r;
    int b_csel = a_t >> 1;

#pragma unroll
    for (int kc = 0; kc < 8; kc++) {
        unsigned a0, a1, a2, a3;
        {
            int chunk = 2 * kc + a_chsel;
            unsigned addr = smem_u32(&sA[a_row * 128 + ((chunk ^ (a_row & 7)) * 8)]);
            asm volatile("ldmatrix.sync.aligned.m8n8.x4.shared.b16 {%0,%1,%2,%3}, [%4];"
                         : "=r"(a0), "=r"(a1), "=r"(a2), "=r"(a3) : "r"(addr));
        }
        int krow = 16 * kc + b_kr;
#pragma unroll
        for (int np = 0; np < 4; np++) {
            unsigned b0, b1, b2, b3;
            int chunk = 2 * np + b_csel;
            unsigned addr = smem_u32(&sW[krow * 64 + ((chunk ^ (krow & 7)) * 8)]);
            asm volatile("ldmatrix.sync.aligned.m8n8.x4.trans.shared.b16 {%0,%1,%2,%3}, [%4];"
                         : "=r"(b0), "=r"(b1), "=r"(b2), "=r"(b3) : "r"(addr));
            asm volatile("mma.sync.aligned.m16n8k16.row.col.f32.f16.f16.f32 "
                         "{%0,%1,%2,%3}, {%4,%5,%6,%7}, {%8,%9}, {%0,%1,%2,%3};"
                         : "+f"(acc[2 * np][0]), "+f"(acc[2 * np][1]),
                           "+f"(acc[2 * np][2]), "+f"(acc[2 * np][3])
                         : "r"(a0), "r"(a1), "r"(a2), "r"(a3), "r"(b0), "r"(b1));
            asm volatile("mma.sync.aligned.m16n8k16.row.col.f32.f16.f16.f32 "
                         "{%0,%1,%2,%3}, {%4,%5,%6,%7}, {%8,%9}, {%0,%1,%2,%3};"
                         : "+f"(acc[2 * np + 1][0]), "+f"(acc[2 * np + 1][1]),
                           "+f"(acc[2 * np + 1][2]), "+f"(acc[2 * np + 1][3])
                         : "r"(a0), "r"(a1), "r"(a2), "r"(a3), "r"(b2), "r"(b3));
        }
    }

    int r0 = wrow + (lane >> 2);
    int cq = lane & 3;
#pragma unroll
    for (int half = 0; half < 2; half++) {
        int node = base0 + r0 + half * 8;
        if (node < NN) {
            float d = g_dis[node];
#pragma unroll
            for (int nt = 0; nt < 8; nt++) {
                float v0 = acc[nt][2 * half + 0] * d;
                float v1 = acc[nt][2 * half + 1] * d;
                g_ha[(size_t)node * 32 + nt * 4 + cq] = __floats2half2_rn(v0, v1);
            }
        }
    }
}

// ---------------------------------------------------------------------------
// Warp-level CSR aggregation core over PADDED segments (multiples of 8).
__device__ __forceinline__ float2 agg_node(const __half2* __restrict__ hin,
                                           int node, int lane) {
    int e = g_rowptr[node];
    int end = g_rowptr[node + 1];

    float2 self = __half22float2(hin[(size_t)node * 32 + lane]);
    float acx = self.x, acy = self.y;
    float bcx = 0.0f, bcy = 0.0f;

    const int* __restrict__ sp = g_srcbuf;
    for (; e < end; e += 8) {
        int4 a = *reinterpret_cast<const int4*>(sp + e);
        int4 b = *reinterpret_cast<const int4*>(sp + e + 4);
        float2 v0 = __half22float2(hin[(size_t)a.x * 32 + lane]);
        float2 v1 = __half22float2(hin[(size_t)a.y * 32 + lane]);
        float2 v2 = __half22float2(hin[(size_t)a.z * 32 + lane]);
        float2 v3 = __half22float2(hin[(size_t)a.w * 32 + lane]);
        float2 v4 = __half22float2(hin[(size_t)b.x * 32 + lane]);
        float2 v5 = __half22float2(hin[(size_t)b.y * 32 + lane]);
        float2 v6 = __half22float2(hin[(size_t)b.z * 32 + lane]);
        float2 v7 = __half22float2(hin[(size_t)b.w * 32 + lane]);
        acx += v0.x; acy += v0.y;
        bcx += v1.x; bcy += v1.y;
        acx += v2.x; acy += v2.y;
        bcx += v3.x; bcy += v3.y;
        acx += v4.x; acy += v4.y;
        bcx += v5.x; bcy += v5.y;
        acx += v6.x; acy += v6.y;
        bcx += v7.x; bcy += v7.y;
    }
    float d = g_dis[node];
    return make_float2(d * (acx + bcx), d * (acy + bcy));
}

// agg1: g_hb = fp16(dis * relu(P ĥa + b1))  (pre-scaled for next gather)
__global__ void k_agg1(const float* __restrict__ bias) {
    int node = blockIdx.x * 8 + (threadIdx.x >> 5);   // 12500*8 == NN exactly
    int lane = threadIdx.x & 31;
    float2 r = agg_node(g_ha, node, lane);
    float2 b = reinterpret_cast<const float2*>(bias)[lane];
    float d = g_dis[node];
    float hx = fmaxf(r.x + b.x, 0.0f);
    float hy = fmaxf(r.y + b.y, 0.0f);
    g_hb[(size_t)node * 32 + lane] = __floats2half2_rn(d * hx, d * hy);
}

// agg2: g_ha = fp16(dis * (P ĥb))  (feeds HMMA gemm2 directly)
__global__ void k_agg2() {
    int node = blockIdx.x * 8 + (threadIdx.x >> 5);
    int lane = threadIdx.x & 31;
    float2 r = agg_node(g_hb, node, lane);
    g_ha[(size_t)node * 32 + lane] = __floats2half2_rn(r.x, r.y);
}

// ---------------------------------------------------------------------------
// mu/lv = agg2 @ [Wmu|Wlv] + [bmu|blv] via HMMA. A = g_ha (fp16, no cvt),
// B = combined 64×64 fp16 W. 256 threads, 128 rows/block, 4 k-chunks.
__global__ void k_gemm2(const float* __restrict__ Wmu, const float* __restrict__ bmu,
                        const float* __restrict__ Wlv, const float* __restrict__ blv,
                        float* __restrict__ out) {
    __shared__ alignas(16) __half sA[128 * 64];    // 16 KB: [row][k] swizzled
    __shared__ alignas(16) __half sW[64 * 64];     // 8 KB:  [k][n]  swizzled
    __shared__ alignas(16) float sB[64];
    int tid = threadIdx.x;
    int base0 = blockIdx.x * 128;

    for (int idx = tid; idx < 64 * 8; idx += 256) {
        int k = idx >> 3, c = idx & 7;
        const float* src = (c < 4) ? (Wmu + k * LAT + c * 8)
                                   : (Wlv + k * LAT + (c - 4) * 8);
        const float4* s4 = reinterpret_cast<const float4*>(src);
        H8 h = cvt8(s4[0], s4[1]);
        *reinterpret_cast<H8*>(&sW[k * 64 + ((c ^ (k & 7)) * 8)]) = h;
    }
    if (tid < 64) sB[tid] = (tid < 32) ? bmu[tid] : blv[tid - 32];
    for (int idx = tid; idx < 128 * 8; idx += 256) {
        int row = idx >> 3, c = idx & 7;
        int grow = base0 + row;
        if (grow >= NN) grow = NN - 1;             // junk ok, stores guarded
        H8 h = *reinterpret_cast<const H8*>(&g_ha[(size_t)grow * 32 + c * 4]);
        *reinterpret_cast<H8*>(&sA[row * 64 + ((c ^ (row & 7)) * 8)]) = h;
    }
    __syncthreads();

    int warp = tid >> 5;
    int lane = tid & 31;
    int wrow = warp * 16;

    float acc[8][4];
#pragma unroll
    for (int n = 0; n < 8; n++)
#pragma unroll
        for (int j = 0; j < 4; j++) acc[n][j] = 0.0f;

    int a_t = lane >> 3, a_r = lane & 7;
    int a_row = wrow + (a_t & 1) * 8 + a_r;
    int a_chsel = a_t >> 1;
    int b_kr = (a_t & 1) * 8 + a_r;
    int b_csel = a_t >> 1;

#pragma unroll
    for (int kc = 0; kc < 4; kc++) {
        unsigned a0, a1, a2, a3;
        {
            int chunk = 2 * kc + a_chsel;
            unsigned addr = smem_u32(&sA[a_row * 64 + ((chunk ^ (a_row & 7)) * 8)]);
            asm volatile("ldmatrix.sync.aligned.m8n8.x4.shared.b16 {%0,%1,%2,%3}, [%4];"
                         : "=r"(a0), "=r"(a1), "=r"(a2), "=r"(a3) : "r"(addr));
        }
        int krow = 16 * kc + b_kr;
#pragma unroll
        for (int np = 0; np < 4; np++) {
            unsigned b0, b1, b2, b3;
            int chunk = 2 * np + b_csel;
            unsigned addr = smem_u32(&sW[krow * 64 + ((chunk ^ (krow & 7)) * 8)]);
            asm volatile("ldmatrix.sync.aligned.m8n8.x4.trans.shared.b16 {%0,%1,%2,%3}, [%4];"
                         : "=r"(b0), "=r"(b1), "=r"(b2), "=r"(b3) : "r"(addr));
            asm volatile("mma.sync.aligned.m16n8k16.row.col.f32.f16.f16.f32 "
                         "{%0,%1,%2,%3}, {%4,%5,%6,%7}, {%8,%9}, {%0,%1,%2,%3};"
                         : "+f"(acc[2 * np][0]), "+f"(acc[2 * np][1]),
                           "+f"(acc[2 * np][2]), "+f"(acc[2 * np][3])
                         : "r"(a0), "r"(a1), "r"(a2), "r"(a3), "r"(b0), "r"(b1));
            asm volatile("mma.sync.aligned.m16n8k16.row.col.f32.f16.f16.f32 "
                         "{%0,%1,%2,%3}, {%4,%5,%6,%7}, {%8,%9}, {%0,%1,%2,%3};"
                         : "+f"(acc[2 * np + 1][0]), "+f"(acc[2 * np + 1][1]),
                           "+f"(acc[2 * np + 1][2]), "+f"(acc[2 * np + 1][3])
                         : "r"(a0), "r"(a1), "r"(a2), "r"(a3), "r"(b2), "r"(b3));
        }
    }

    // Epilogue: c = nt*8 + (lane&3)*2 (+1). nt<4 → mu, nt>=4 → lv.
    int r0 = wrow + (lane >> 2);
    int cq = lane & 3;
#pragma unroll
    for (int half = 0; half < 2; half++) {
        int node = base0 + r0 + half * 8;
        if (node < NN) {
#pragma unroll
            for (int nt = 0; nt < 8; nt++) {
                int c = nt * 8 + cq * 2;
                float2 v;
                v.x = acc[nt][2 * half + 0] + sB[c];
                v.y = acc[nt][2 * half + 1] + sB[c + 1];
                if (c < 32)
                    *reinterpret_cast<float2*>(&out[(size_t)node * LAT + c]) = v;
                else
                    *reinterpret_cast<float2*>(
                        &out[(size_t)NN * LAT + (size_t)node * LAT + (c - 32)]) = v;
            }
        }
    }
}

// ---------------------------------------------------------------------------
extern "C" void kernel_launch(void* const* d_in, const int* in_sizes, int n_in,
                              void* d_out, int out_size) {
    const float* x    = (const float*)d_in[0];
    const int*   ei   = (const int*)d_in[1];    // int32 or int64 (detected)
    const float* W1   = (const float*)d_in[2];
    const float* b1   = (const float*)d_in[3];
    const float* Wmu  = (const float*)d_in[4];
    const float* bmu  = (const float*)d_in[5];
    const float* Wlv  = (const float*)d_in[6];
    const float* blv  = (const float*)d_in[7];
    float*       out  = (float*)d_out;

    k_zero_detect<<<(NN + 255) / 256, 256>>>(ei);       // 1
    k_count_deg<<<(NE + 255) / 256, 256>>>(ei);         // 2
    k_scan_local<<<SCAN_NB, SCAN_BLK>>>();              // 3 (also dis)
    k_finalize_csr<<<(NN + 255) / 256, 256>>>();        // 4
    k_gemm1_scatter<<<GB1 + SCAT_BLKS, 256>>>(x, W1, ei);  // 5 (concurrent works)
    k_agg1<<<NN / 8, 256>>>(b1);                        // 6
    k_agg2<<<NN / 8, 256>>>();                          // 7
    k_gemm2<<<(NN + 127) / 128, 256>>>(Wmu, bmu, Wlv, blv, out);  // 8
}

// round 17
// speedup vs baseline: 1.1357x; 1.0135x over previous
#include <cuda_runtime.h>
#include <cuda_fp16.h>

#define NN 100000
#define NE 1600000
#define IN_CH 128
#define HID 64
#define LAT 32

#define SCAN_BLK 512
#define SCAN_NB ((NN + SCAN_BLK - 1) / SCAN_BLK)   // 196
#define NEP (NE + 8 * NN)                          // padded edge capacity
#define GB1 ((NN + 127) / 128)                     // 782 gemm1 blocks
#define SCAT_BLKS ((NE + 1023) / 1024)             // 1563 scatter blocks

// Scratch (static __device__ — no allocations allowed).
// g_deg is zeroed by k_gemm2's tail for the NEXT execution; it is zero at
// module load, so every execution sees g_deg == 0 on entry (graph capture
// does not execute kernels). Deterministic: identical work every call.
__device__ int     g_deg[NN];
__device__ int     g_rowptr[NN + 1];      // padded CSR offsets (multiples of 8)
__device__ int     g_cursor[NN];
__device__ int     g_blocksums[SCAN_NB];
__device__ int     g_srcbuf[NEP];         // per-edge source index (pad = NN)
__device__ float   g_dis[NN];
__device__ __half2 g_ha[(NN + 1) * 32];   // dis*h1 fp16; later agg2 out (fp16)
__device__ __half2 g_hb[(NN + 1) * 32];   // dis*relu(...) fp16; ghost stays 0

struct alignas(16) H8 { __half2 h[4]; };

// ---------------------------------------------------------------------------
__device__ __forceinline__ unsigned smem_u32(const void* p) {
    return (unsigned)__cvta_generic_to_shared(p);
}
__device__ __forceinline__ H8 cvt8(float4 f0, float4 f1) {
    H8 h;
    h.h[0] = __floats2half2_rn(f0.x, f0.y);
    h.h[1] = __floats2half2_rn(f0.z, f0.w);
    h.h[2] = __floats2half2_rn(f1.x, f1.y);
    h.h[3] = __floats2half2_rn(f1.z, f1.w);
    return h;
}

// Per-warp edge_index dtype detection: int64 values < 2^31 have all-zero odd
// 32-bit words. First 256B of ei are L1/L2-hot — effectively free.
__device__ __forceinline__ int detect_stride(const int* __restrict__ ei) {
    int lane = threadIdx.x & 31;
    int v = ei[2 * lane + 1];
    unsigned m = __ballot_sync(0xffffffffu, v != 0);
    return (m == 0u) ? 2 : 1;
}

// ---------------------------------------------------------------------------
// Degree histogram: 4 edges/thread, batched loads (MLP 4) before atomics.
__global__ void k_count_deg(const int* __restrict__ ei) {
    int st = detect_stride(ei);
    int base = blockIdx.x * 1024 + threadIdx.x;
    int cc[4];
#pragma unroll
    for (int j = 0; j < 4; j++) {
        int e = base + j * 256;
        int es = (e < NE) ? e : NE - 1;
        cc[j] = ei[(size_t)st * NE + (size_t)es * st];
    }
#pragma unroll
    for (int j = 0; j < 4; j++) {
        int e = base + j * 256;
        if (e < NE) atomicAdd(&g_deg[cc[j]], 1);
    }
}

// Per-block exclusive scan of PADDED degrees -> g_rowptr (local part).
// Also computes dis = rsqrt(deg+1).
__global__ void k_scan_local() {
    __shared__ int s[SCAN_BLK];
    int t = threadIdx.x;
    int i = blockIdx.x * SCAN_BLK + t;
    int deg = (i < NN) ? g_deg[i] : 0;
    if (i < NN) g_dis[i] = rsqrtf((float)deg + 1.0f);
    int v = (deg + 7) & ~7;                          // pad to multiple of 8
    s[t] = v;
    __syncthreads();
#pragma unroll
    for (int off = 1; off < SCAN_BLK; off <<= 1) {
        int add = (t >= off) ? s[t - off] : 0;
        __syncthreads();
        s[t] += add;
        __syncthreads();
    }
    if (i < NN) g_rowptr[i] = s[t] - v;   // exclusive (local)
    if (t == SCAN_BLK - 1) g_blocksums[blockIdx.x] = s[t];
}

// Finalize: every block redundantly scans the 196 block sums in smem, then
// rowptr += prefix; cursor = rowptr; pad slots get ghost source NN.
__global__ void k_finalize_csr() {
    __shared__ int s[256];
    int t = threadIdx.x;
    int bv = (t < SCAN_NB) ? g_blocksums[t] : 0;
    s[t] = bv;
    __syncthreads();
#pragma unroll
    for (int off = 1; off < 256; off <<= 1) {
        int add = (t >= off) ? s[t - off] : 0;
        __syncthreads();
        s[t] += add;
        __syncthreads();
    }
    int i = blockIdx.x * blockDim.x + t;
    if (i < NN) {
        int sb = i >> 9;
        int prefix = (sb > 0) ? s[sb - 1] : 0;
        int rp = g_rowptr[i] + prefix;
        g_rowptr[i] = rp;
        g_cursor[i] = rp;
        int deg = g_deg[i];
        int pdeg = (deg + 7) & ~7;
        for (int j = rp + deg; j < rp + pdeg; j++)
            g_srcbuf[j] = NN;                        // ghost node: features 0
    }
    if (i == 0) g_rowptr[NN] = s[SCAN_NB - 1];
}

// ---------------------------------------------------------------------------
// FAT KERNEL: blocks [0, GB1) run gemm1 (h1 = x@W1 via HMMA, ĥ→g_ha);
// blocks [GB1, GB1+SCAT_BLKS) run edge scatter (4 edges/thread, batched).
// The two works are independent and run concurrently on the SM pool.
__global__ void k_gemm1_scatter(const float* __restrict__ x,
                                const float* __restrict__ W,
                                const int* __restrict__ ei) {
    __shared__ alignas(16) __half sA[128 * 128];   // 32 KB: [row][k] swizzled
    __shared__ alignas(16) __half sW[128 * 64];    // 16 KB: [k][n]  swizzled
    int tid = threadIdx.x;

    if (blockIdx.x >= GB1) {
        // ---- scatter path ----
        int st = detect_stride(ei);
        int base = (blockIdx.x - GB1) * 1024 + tid;
        int rr[4], cc[4];
#pragma unroll
        for (int j = 0; j < 4; j++) {
            int e = base + j * 256;
            int es = (e < NE) ? e : NE - 1;
            rr[j] = ei[(size_t)es * st];
            cc[j] = ei[(size_t)st * NE + (size_t)es * st];
        }
#pragma unroll
        for (int j = 0; j < 4; j++) {
            int e = base + j * 256;
            if (e < NE) {
                int pos = atomicAdd(&g_cursor[cc[j]], 1);
                g_srcbuf[pos] = rr[j];
            }
        }
        return;
    }

    // ---- gemm1 path ----
    int base0 = blockIdx.x * 128;

    // Stage x tile with deep MLP: 2048 chunks, 2 batches × (8 LDG.128 → cvt/STS).
#pragma unroll
    for (int b = 0; b < 2; b++) {
        float4 f[8];
#pragma unroll
        for (int q = 0; q < 4; q++) {
            int idx = tid + (b * 4 + q) * 256;
            int row = idx >> 4, c = idx & 15;
            int grow = base0 + row;
            if (grow >= NN) grow = NN - 1;         // junk ok, stores guarded
            const float4* src = reinterpret_cast<const float4*>(
                x + (size_t)grow * IN_CH + c * 8);
            f[2 * q] = src[0];
            f[2 * q + 1] = src[1];
        }
#pragma unroll
        for (int q = 0; q < 4; q++) {
            int idx = tid + (b * 4 + q) * 256;
            int row = idx >> 4, c = idx & 15;
            H8 h = cvt8(f[2 * q], f[2 * q + 1]);
            *reinterpret_cast<H8*>(&sA[row * 128 + ((c ^ (row & 7)) * 8)]) = h;
        }
    }
    // Stage W tile: 1024 chunks; chunk (k, c) at k*128B + (c^(k&7))*16B.
    for (int idx = tid; idx < 128 * 8; idx += 256) {
        int k = idx >> 3, c = idx & 7;
        const float4* src = reinterpret_cast<const float4*>(W + k * HID + c * 8);
        H8 h = cvt8(src[0], src[1]);
        *reinterpret_cast<H8*>(&sW[k * 64 + ((c ^ (k & 7)) * 8)]) = h;
    }
    __syncthreads();

    int warp = tid >> 5;
    int lane = tid & 31;
    int wrow = warp * 16;

    float acc[8][4];
#pragma unroll
    for (int n = 0; n < 8; n++)
#pragma unroll
        for (int j = 0; j < 4; j++) acc[n][j] = 0.0f;

    int a_t = lane >> 3, a_r = lane & 7;
    int a_row = wrow + (a_t & 1) * 8 + a_r;
    int a_chsel = a_t >> 1;
    int b_kr = (a_t & 1) * 8 + a_r;
    int b_csel = a_t >> 1;

#pragma unroll
    for (int kc = 0; kc < 8; kc++) {
        unsigned a0, a1, a2, a3;
        {
            int chunk = 2 * kc + a_chsel;
            unsigned addr = smem_u32(&sA[a_row * 128 + ((chunk ^ (a_row & 7)) * 8)]);
            asm volatile("ldmatrix.sync.aligned.m8n8.x4.shared.b16 {%0,%1,%2,%3}, [%4];"
                         : "=r"(a0), "=r"(a1), "=r"(a2), "=r"(a3) : "r"(addr));
        }
        int krow = 16 * kc + b_kr;
#pragma unroll
        for (int np = 0; np < 4; np++) {
            unsigned b0, b1, b2, b3;
            int chunk = 2 * np + b_csel;
            unsigned addr = smem_u32(&sW[krow * 64 + ((chunk ^ (krow & 7)) * 8)]);
            asm volatile("ldmatrix.sync.aligned.m8n8.x4.trans.shared.b16 {%0,%1,%2,%3}, [%4];"
                         : "=r"(b0), "=r"(b1), "=r"(b2), "=r"(b3) : "r"(addr));
            asm volatile("mma.sync.aligned.m16n8k16.row.col.f32.f16.f16.f32 "
                         "{%0,%1,%2,%3}, {%4,%5,%6,%7}, {%8,%9}, {%0,%1,%2,%3};"
                         : "+f"(acc[2 * np][0]), "+f"(acc[2 * np][1]),
                           "+f"(acc[2 * np][2]), "+f"(acc[2 * np][3])
                         : "r"(a0), "r"(a1), "r"(a2), "r"(a3), "r"(b0), "r"(b1));
            asm volatile("mma.sync.aligned.m16n8k16.row.col.f32.f16.f16.f32 "
                         "{%0,%1,%2,%3}, {%4,%5,%6,%7}, {%8,%9}, {%0,%1,%2,%3};"
                         : "+f"(acc[2 * np + 1][0]), "+f"(acc[2 * np + 1][1]),
                           "+f"(acc[2 * np + 1][2]), "+f"(acc[2 * np + 1][3])
                         : "r"(a0), "r"(a1), "r"(a2), "r"(a3), "r"(b2), "r"(b3));
        }
    }

    int r0 = wrow + (lane >> 2);
    int cq = lane & 3;
#pragma unroll
    for (int half = 0; half < 2; half++) {
        int node = base0 + r0 + half * 8;
        if (node < NN) {
            float d = g_dis[node];
#pragma unroll
            for (int nt = 0; nt < 8; nt++) {
                float v0 = acc[nt][2 * half + 0] * d;
                float v1 = acc[nt][2 * half + 1] * d;
                g_ha[(size_t)node * 32 + nt * 4 + cq] = __floats2half2_rn(v0, v1);
            }
        }
    }
}

// ---------------------------------------------------------------------------
// Warp-level CSR aggregation core over PADDED segments (multiples of 8).
__device__ __forceinline__ float2 agg_node(const __half2* __restrict__ hin,
                                           int node, int lane) {
    int e = g_rowptr[node];
    int end = g_rowptr[node + 1];

    float2 self = __half22float2(hin[(size_t)node * 32 + lane]);
    float acx = self.x, acy = self.y;
    float bcx = 0.0f, bcy = 0.0f;

    const int* __restrict__ sp = g_srcbuf;
    for (; e < end; e += 8) {
        int4 a = *reinterpret_cast<const int4*>(sp + e);
        int4 b = *reinterpret_cast<const int4*>(sp + e + 4);
        float2 v0 = __half22float2(hin[(size_t)a.x * 32 + lane]);
        float2 v1 = __half22float2(hin[(size_t)a.y * 32 + lane]);
        float2 v2 = __half22float2(hin[(size_t)a.z * 32 + lane]);
        float2 v3 = __half22float2(hin[(size_t)a.w * 32 + lane]);
        float2 v4 = __half22float2(hin[(size_t)b.x * 32 + lane]);
        float2 v5 = __half22float2(hin[(size_t)b.y * 32 + lane]);
        float2 v6 = __half22float2(hin[(size_t)b.z * 32 + lane]);
        float2 v7 = __half22float2(hin[(size_t)b.w * 32 + lane]);
        acx += v0.x; acy += v0.y;
        bcx += v1.x; bcy += v1.y;
        acx += v2.x; acy += v2.y;
        bcx += v3.x; bcy += v3.y;
        acx += v4.x; acy += v4.y;
        bcx += v5.x; bcy += v5.y;
        acx += v6.x; acy += v6.y;
        bcx += v7.x; bcy += v7.y;
    }
    float d = g_dis[node];
    return make_float2(d * (acx + bcx), d * (acy + bcy));
}

// agg1: g_hb = fp16(dis * relu(P ĥa + b1))  (pre-scaled for next gather)
__global__ void k_agg1(const float* __restrict__ bias) {
    int node = blockIdx.x * 8 + (threadIdx.x >> 5);   // 12500*8 == NN exactly
    int lane = threadIdx.x & 31;
    float2 r = agg_node(g_ha, node, lane);
    float2 b = reinterpret_cast<const float2*>(bias)[lane];
    float d = g_dis[node];
    float hx = fmaxf(r.x + b.x, 0.0f);
    float hy = fmaxf(r.y + b.y, 0.0f);
    g_hb[(size_t)node * 32 + lane] = __floats2half2_rn(d * hx, d * hy);
}

// agg2: g_ha = fp16(dis * (P ĥb))  (feeds HMMA gemm2 directly)
__global__ void k_agg2() {
    int node = blockIdx.x * 8 + (threadIdx.x >> 5);
    int lane = threadIdx.x & 31;
    float2 r = agg_node(g_hb, node, lane);
    g_ha[(size_t)node * 32 + lane] = __floats2half2_rn(r.x, r.y);
}

// ---------------------------------------------------------------------------
// mu/lv = agg2 @ [Wmu|Wlv] + [bmu|blv] via HMMA. A = g_ha (fp16, no cvt),
// B = combined 64×64 fp16 W. 256 threads, 128 rows/block, 4 k-chunks.
// Tail: zero g_deg for the next execution (graph replay).
__global__ void k_gemm2(const float* __restrict__ Wmu, const float* __restrict__ bmu,
                        const float* __restrict__ Wlv, const float* __restrict__ blv,
                        float* __restrict__ out) {
    __shared__ alignas(16) __half sA[128 * 64];    // 16 KB: [row][k] swizzled
    __shared__ alignas(16) __half sW[64 * 64];     // 8 KB:  [k][n]  swizzled
    __shared__ alignas(16) float sB[64];
    int tid = threadIdx.x;
    int base0 = blockIdx.x * 128;

    for (int idx = tid; idx < 64 * 8; idx += 256) {
        int k = idx >> 3, c = idx & 7;
        const float* src = (c < 4) ? (Wmu + k * LAT + c * 8)
                                   : (Wlv + k * LAT + (c - 4) * 8);
        const float4* s4 = reinterpret_cast<const float4*>(src);
        H8 h = cvt8(s4[0], s4[1]);
        *reinterpret_cast<H8*>(&sW[k * 64 + ((c ^ (k & 7)) * 8)]) = h;
    }
    if (tid < 64) sB[tid] = (tid < 32) ? bmu[tid] : blv[tid - 32];
    for (int idx = tid; idx < 128 * 8; idx += 256) {
        int row = idx >> 3, c = idx & 7;
        int grow = base0 + row;
        if (grow >= NN) grow = NN - 1;             // junk ok, stores guarded
        H8 h = *reinterpret_cast<const H8*>(&g_ha[(size_t)grow * 32 + c * 4]);
        *reinterpret_cast<H8*>(&sA[row * 64 + ((c ^ (row & 7)) * 8)]) = h;
    }
    __syncthreads();

    int warp = tid >> 5;
    int lane = tid & 31;
    int wrow = warp * 16;

    float acc[8][4];
#pragma unroll
    for (int n = 0; n < 8; n++)
#pragma unroll
        for (int j = 0; j < 4; j++) acc[n][j] = 0.0f;

    int a_t = lane >> 3, a_r = lane & 7;
    int a_row = wrow + (a_t & 1) * 8 + a_r;
    int a_chsel = a_t >> 1;
    int b_kr = (a_t & 1) * 8 + a_r;
    int b_csel = a_t >> 1;

#pragma unroll
    for (int kc = 0; kc < 4; kc++) {
        unsigned a0, a1, a2, a3;
        {
            int chunk = 2 * kc + a_chsel;
            unsigned addr = smem_u32(&sA[a_row * 64 + ((chunk ^ (a_row & 7)) * 8)]);
            asm volatile("ldmatrix.sync.aligned.m8n8.x4.shared.b16 {%0,%1,%2,%3}, [%4];"
                         : "=r"(a0), "=r"(a1), "=r"(a2), "=r"(a3) : "r"(addr));
        }
        int krow = 16 * kc + b_kr;
#pragma unroll
        for (int np = 0; np < 4; np++) {
            unsigned b0, b1, b2, b3;
            int chunk = 2 * np + b_csel;
            unsigned addr = smem_u32(&sW[krow * 64 + ((chunk ^ (krow & 7)) * 8)]);
            asm volatile("ldmatrix.sync.aligned.m8n8.x4.trans.shared.b16 {%0,%1,%2,%3}, [%4];"
                         : "=r"(b0), "=r"(b1), "=r"(b2), "=r"(b3) : "r"(addr));
            asm volatile("mma.sync.aligned.m16n8k16.row.col.f32.f16.f16.f32 "
                         "{%0,%1,%2,%3}, {%4,%5,%6,%7}, {%8,%9}, {%0,%1,%2,%3};"
                         : "+f"(acc[2 * np][0]), "+f"(acc[2 * np][1]),
                           "+f"(acc[2 * np][2]), "+f"(acc[2 * np][3])
                         : "r"(a0), "r"(a1), "r"(a2), "r"(a3), "r"(b0), "r"(b1));
            asm volatile("mma.sync.aligned.m16n8k16.row.col.f32.f16.f16.f32 "
                         "{%0,%1,%2,%3}, {%4,%5,%6,%7}, {%8,%9}, {%0,%1,%2,%3};"
                         : "+f"(acc[2 * np + 1][0]), "+f"(acc[2 * np + 1][1]),
                           "+f"(acc[2 * np + 1][2]), "+f"(acc[2 * np + 1][3])
                         : "r"(a0), "r"(a1), "r"(a2), "r"(a3), "r"(b2), "r"(b3));
        }
    }

    // Epilogue: c = nt*8 + (lane&3)*2 (+1). nt<4 → mu, nt>=4 → lv.
    int r0 = wrow + (lane >> 2);
    int cq = lane & 3;
#pragma unroll
    for (int half = 0; half < 2; half++) {
        int node = base0 + r0 + half * 8;
        if (node < NN) {
#pragma unroll
            for (int nt = 0; nt < 8; nt++) {
                int c = nt * 8 + cq * 2;
                float2 v;
                v.x = acc[nt][2 * half + 0] + sB[c];
                v.y = acc[nt][2 * half + 1] + sB[c + 1];
                if (c < 32)
                    *reinterpret_cast<float2*>(&out[(size_t)node * LAT + c]) = v;
                else
                    *reinterpret_cast<float2*>(
                        &out[(size_t)NN * LAT + (size_t)node * LAT + (c - 32)]) = v;
            }
        }
    }

    // Tail: zero g_deg for the next execution.
    int total = gridDim.x * blockDim.x;              // 782*256 = 200192 ≥ NN
    for (int i = blockIdx.x * blockDim.x + tid; i < NN; i += total)
        g_deg[i] = 0;
}

// ---------------------------------------------------------------------------
extern "C" void kernel_launch(void* const* d_in, const int* in_sizes, int n_in,
                              void* d_out, int out_size) {
    const float* x    = (const float*)d_in[0];
    const int*   ei   = (const int*)d_in[1];    // int32 or int64 (detected)
    const float* W1   = (const float*)d_in[2];
    const float* b1   = (const float*)d_in[3];
    const float* Wmu  = (const float*)d_in[4];
    const float* bmu  = (const float*)d_in[5];
    const float* Wlv  = (const float*)d_in[6];
    const float* blv  = (const float*)d_in[7];
    float*       out  = (float*)d_out;

    k_count_deg<<<(NE + 1023) / 1024, 256>>>(ei);       // 1
    k_scan_local<<<SCAN_NB, SCAN_BLK>>>();              // 2 (also dis)
    k_finalize_csr<<<(NN + 255) / 256, 256>>>();        // 3
    k_gemm1_scatter<<<GB1 + SCAT_BLKS, 256>>>(x, W1, ei);  // 4 ← ncu slot
    k_agg1<<<NN / 8, 256>>>(b1);                        // 5
    k_agg2<<<NN / 8, 256>>>();                          // 6
    k_gemm2<<<(NN + 127) / 128, 256>>>(Wmu, bmu, Wlv, blv, out);  // 7 (+deg reset)
}